// round 13
// baseline (speedup 1.0000x reference)
#include <cuda_runtime.h>
#include <cuda_bf16.h>
#include <cuda_fp16.h>
#include <math.h>
#include <stdint.h>

// ---------------------------------------------------------------------------
// GATv2 layer. GEMMs via mma.sync bf16 (3-term hi/lo split, fp32 accum),
// term-outer mainloop, cp.async double-buffered A, pre-split x.
// fs stored fp16 -> node edge-gather traffic halved (256 B/warp/edge).
// ---------------------------------------------------------------------------

#define N_NODES 50000
#define E_EDGES 800000
#define F_DIM   128
#define NEG_SLOPE 0.2f
#define LN_EPS  1e-12f
#define NT64    ((N_NODES + 63) / 64)    // 782 tiles of 64 rows

#define CX_BLOCKS   6250
#define CW_BLOCKS   2
#define HIST_BLOCKS 782
#define PREP_BLOCKS (CX_BLOCKS + CW_BLOCKS + HIST_BLOCKS)

// ---- device scratch ----
__device__ __half g_fs_h[(size_t)N_NODES * F_DIM];   // fs in fp16
__device__ float  g_fd[(size_t)N_NODES * F_DIM];
__device__ int    g_deg[N_NODES];          // static-zero on call 1; scan1 re-zeros
__device__ int    g_rowptr[N_NODES + 1];
__device__ int    g_cursor[N_NODES];
__device__ int    g_src_sorted[E_EDGES];
__device__ int    g_blocksums[64];
__device__ __nv_bfloat16 g_wt_hi[2][128 * 128];
__device__ __nv_bfloat16 g_wt_lo[2][128 * 128];
__device__ __nv_bfloat16 g_x_hi[(size_t)N_NODES * F_DIM];
__device__ __nv_bfloat16 g_x_lo[(size_t)N_NODES * F_DIM];

__device__ __forceinline__ uint32_t smem_u32(const void* p) {
    uint32_t a;
    asm("{ .reg .u64 t; cvta.to.shared.u64 t, %1; cvt.u32.u64 %0, t; }"
        : "=r"(a) : "l"(p));
    return a;
}
__device__ __forceinline__ uint32_t pack2(float a, float b) {
    __nv_bfloat162 t = __floats2bfloat162_rn(a, b);
    return *reinterpret_cast<uint32_t*>(&t);
}
__device__ __forceinline__ void ldsm_x4(uint32_t* r, uint32_t addr) {
    asm volatile("ldmatrix.sync.aligned.m8n8.x4.shared.b16 {%0,%1,%2,%3}, [%4];"
                 : "=r"(r[0]), "=r"(r[1]), "=r"(r[2]), "=r"(r[3]) : "r"(addr));
}
__device__ __forceinline__ void mma_bf16(float* d, const uint32_t* a,
                                         uint32_t b0, uint32_t b1) {
    asm volatile(
        "mma.sync.aligned.m16n8k16.row.col.f32.bf16.bf16.f32 "
        "{%0,%1,%2,%3}, {%4,%5,%6,%7}, {%8,%9}, {%0,%1,%2,%3};"
        : "+f"(d[0]), "+f"(d[1]), "+f"(d[2]), "+f"(d[3])
        : "r"(a[0]), "r"(a[1]), "r"(a[2]), "r"(a[3]), "r"(b0), "r"(b1));
}
__device__ __forceinline__ void cp_async16(uint32_t saddr, const void* gaddr, int srcsz) {
    asm volatile("cp.async.cg.shared.global [%0], [%1], 16, %2;"
                 :: "r"(saddr), "l"(gaddr), "r"(srcsz) : "memory");
}
#define CP_COMMIT() asm volatile("cp.async.commit_group;" ::: "memory")
#define CP_WAIT1()  asm volatile("cp.async.wait_group 1;" ::: "memory")

// ---------------------------------------------------------------------------
// prep: convert_x | convert_w | hist
// ---------------------------------------------------------------------------
__global__ __launch_bounds__(256) void prep_kernel(
    const float* __restrict__ x,
    const float* __restrict__ Wsrc, const float* __restrict__ Wdst,
    const int* __restrict__ dst)
{
    const int b = blockIdx.x, tid = threadIdx.x;
    if (b < CX_BLOCKS) {
        size_t i4 = (size_t)b * 256 + tid;
        float4 v = ((const float4*)x)[i4];
        __nv_bfloat162 h01 = __floats2bfloat162_rn(v.x, v.y);
        __nv_bfloat162 h23 = __floats2bfloat162_rn(v.z, v.w);
        uint2 hi, lo;
        hi.x = *reinterpret_cast<uint32_t*>(&h01);
        hi.y = *reinterpret_cast<uint32_t*>(&h23);
        lo.x = pack2(v.x - __bfloat162float(h01.x), v.y - __bfloat162float(h01.y));
        lo.y = pack2(v.z - __bfloat162float(h23.x), v.w - __bfloat162float(h23.y));
        ((uint2*)g_x_hi)[i4] = hi;
        ((uint2*)g_x_lo)[i4] = lo;
    } else if (b < CX_BLOCKS + CW_BLOCKS) {
        const int w = b - CX_BLOCKS;
        const float* W = w == 0 ? Wsrc : Wdst;
        for (int idx = tid; idx < 128 * 128; idx += 256) {
            int k = idx >> 7, n = idx & 127;
            float v = W[idx];
            __nv_bfloat16 hi = __float2bfloat16(v);
            float r = v - __bfloat162float(hi);
            g_wt_hi[w][n * 128 + k] = hi;
            g_wt_lo[w][n * 128 + k] = __float2bfloat16(r);
        }
    } else {
        int e4 = (b - CX_BLOCKS - CW_BLOCKS) * 256 + tid;
        if (e4 < E_EDGES / 4) {
            int4 d = ((const int4*)dst)[e4];
            atomicAdd(&g_deg[d.x], 1);
            atomicAdd(&g_deg[d.y], 1);
            atomicAdd(&g_deg[d.z], 1);
            atomicAdd(&g_deg[d.w], 1);
        }
    }
}

// ---------------------------------------------------------------------------
// Persistent GEMM: 148 CTAs, 1/SM; both projections per CTA; term-outer loop.
// fs (wsel=0) written as fp16; fd (wsel=1) as fp32.
// ---------------------------------------------------------------------------
#define PAD   136
#define A_IMG (64 * PAD)
#define B_IMG (128 * PAD)
#define B_BASE (4 * A_IMG)
#define SM_TOTAL ((4 * A_IMG + 4 * B_IMG) * 2)   // 208896 bytes

__global__ __launch_bounds__(256, 1) void gemm_mma_kernel(
    const float* __restrict__ bsrc, const float* __restrict__ bdst)
{
    extern __shared__ __nv_bfloat16 sm[];
    const int tid = threadIdx.x, wid = tid >> 5, lane = tid & 31;
    const int wm = wid >> 2, wn = wid & 3;
    const uint32_t sbase = smem_u32(sm);

    for (int i = tid; i < 2048; i += 256) {
        int n = i >> 4, k = (i & 15) << 3;
        *(float4*)(sm + B_BASE + 0 * B_IMG + n * PAD + k) = *(const float4*)(g_wt_hi[0] + n * 128 + k);
        *(float4*)(sm + B_BASE + 1 * B_IMG + n * PAD + k) = *(const float4*)(g_wt_lo[0] + n * 128 + k);
        *(float4*)(sm + B_BASE + 2 * B_IMG + n * PAD + k) = *(const float4*)(g_wt_hi[1] + n * 128 + k);
        *(float4*)(sm + B_BASE + 3 * B_IMG + n * PAD + k) = *(const float4*)(g_wt_lo[1] + n * 128 + k);
    }

    auto prefetch = [&](int tile, int buf) {
        const int row0 = tile * 64;
#pragma unroll
        for (int img = 0; img < 2; img++) {
            const __nv_bfloat16* gx = img ? g_x_lo : g_x_hi;
            uint32_t base = sbase + (uint32_t)((buf * 2 + img) * A_IMG) * 2;
#pragma unroll
            for (int i = tid; i < 1024; i += 256) {
                int row = i >> 4, ch = (i & 15) << 3;
                int gr = row0 + row;
                int sz = (gr < N_NODES) ? 16 : 0;
                cp_async16(base + (uint32_t)(row * PAD + ch) * 2,
                           gx + (size_t)gr * F_DIM + ch, sz);
            }
        }
    };

    const int g = lane >> 3, l7 = lane & 7;
    const int tile0 = blockIdx.x;

    prefetch(tile0, 0);
    CP_COMMIT();

    int ibuf = 0;
    for (int tile = tile0; tile < NT64; tile += 148, ibuf ^= 1) {
        int tnext = tile + 148;
        if (tnext < NT64) prefetch(tnext, ibuf ^ 1);
        CP_COMMIT();
        CP_WAIT1();
        __syncthreads();

        const int row0 = tile * 64;
        const uint32_t ahi = sbase + (uint32_t)((ibuf * 2 + 0) * A_IMG) * 2;
        const uint32_t alo = sbase + (uint32_t)((ibuf * 2 + 1) * A_IMG) * 2;

        for (int wsel = 0; wsel < 2; wsel++) {
            float acc[2][4][4];
#pragma unroll
            for (int i = 0; i < 2; i++)
#pragma unroll
                for (int j = 0; j < 4; j++)
#pragma unroll
                    for (int q = 0; q < 4; q++) acc[i][j][q] = 0.f;

#pragma unroll
            for (int term = 0; term < 3; term++) {
                const uint32_t abase = (term == 2) ? alo : ahi;
                const uint32_t bbase = sbase +
                    (uint32_t)(B_BASE + (wsel * 2 + (term == 1)) * B_IMG) * 2;
#pragma unroll
                for (int k0 = 0; k0 < 128; k0 += 16) {
                    uint32_t afr[2][4];
#pragma unroll
                    for (int mt = 0; mt < 2; mt++) {
                        int r = wm * 32 + mt * 16 + ((g & 1) << 3) + l7;
                        int c = k0 + ((g >> 1) << 3);
                        ldsm_x4(afr[mt], abase + (uint32_t)(r * PAD + c) * 2);
                    }
#pragma unroll
                    for (int nt = 0; nt < 2; nt++) {
                        int r = wn * 32 + nt * 16 + ((g >> 1) << 3) + l7;
                        int c = k0 + ((g & 1) << 3);
                        uint32_t bfr[4];
                        ldsm_x4(bfr, bbase + (uint32_t)(r * PAD + c) * 2);
#pragma unroll
                        for (int mt = 0; mt < 2; mt++) {
                            mma_bf16(acc[mt][nt * 2],     afr[mt], bfr[0], bfr[1]);
                            mma_bf16(acc[mt][nt * 2 + 1], afr[mt], bfr[2], bfr[3]);
                        }
                    }
                }
            }

            const float* bias = wsel ? bdst : bsrc;
#pragma unroll
            for (int mt = 0; mt < 2; mt++) {
#pragma unroll
                for (int j = 0; j < 4; j++) {
                    int col = wn * 32 + (j >> 1) * 16 + (j & 1) * 8 + (lane & 3) * 2;
                    float bx = bias[col], by = bias[col + 1];
                    int r0 = row0 + wm * 32 + mt * 16 + (lane >> 2);
                    int r1 = r0 + 8;
                    if (wsel == 0) {
                        if (r0 < N_NODES) {
                            __half2 h = __floats2half2_rn(acc[mt][j][0] + bx, acc[mt][j][1] + by);
                            *(__half2*)(g_fs_h + (size_t)r0 * F_DIM + col) = h;
                        }
                        if (r1 < N_NODES) {
                            __half2 h = __floats2half2_rn(acc[mt][j][2] + bx, acc[mt][j][3] + by);
                            *(__half2*)(g_fs_h + (size_t)r1 * F_DIM + col) = h;
                        }
                    } else {
                        if (r0 < N_NODES) {
                            float2 o = make_float2(acc[mt][j][0] + bx, acc[mt][j][1] + by);
                            *(float2*)(g_fd + (size_t)r0 * F_DIM + col) = o;
                        }
                        if (r1 < N_NODES) {
                            float2 o = make_float2(acc[mt][j][2] + bx, acc[mt][j][3] + by);
                            *(float2*)(g_fd + (size_t)r1 * F_DIM + col) = o;
                        }
                    }
                }
            }
        }
        __syncthreads();
    }
}

// ---------------------------------------------------------------------------
// scan1: block-local exclusive scan of degrees; RESETS g_deg for next call.
// ---------------------------------------------------------------------------
__global__ __launch_bounds__(1024) void scan1_kernel() {
    __shared__ int ws[32];
    const int tid = threadIdx.x, lane = tid & 31, wid = tid >> 5;
    int i = blockIdx.x * 1024 + tid;
    int v = 0;
    if (i < N_NODES) { v = g_deg[i]; g_deg[i] = 0; }
    int xv = v;
#pragma unroll
    for (int d = 1; d < 32; d <<= 1) {
        int t = __shfl_up_sync(0xffffffffu, xv, d);
        if (lane >= d) xv += t;
    }
    if (lane == 31) ws[wid] = xv;
    __syncthreads();
    if (wid == 0) {
        int y = ws[lane];
#pragma unroll
        for (int d = 1; d < 32; d <<= 1) {
            int t = __shfl_up_sync(0xffffffffu, y, d);
            if (lane >= d) y += t;
        }
        ws[lane] = y;
    }
    __syncthreads();
    int off = (wid > 0) ? ws[wid - 1] : 0;
    int incl = xv + off;
    if (i < N_NODES) g_rowptr[i] = incl - v;
    if (tid == 1023) g_blocksums[blockIdx.x] = incl;
}

// ---------------------------------------------------------------------------
// scan3: inline scan of 49 block sums + fixup.
// ---------------------------------------------------------------------------
__global__ __launch_bounds__(1024) void scan3_kernel() {
    __shared__ int s[64];
    const int tid = threadIdx.x;
    if (tid < 64) {
        int v = (tid < 49) ? g_blocksums[tid] : 0;
        int xv = v;
#pragma unroll
        for (int d = 1; d < 32; d <<= 1) {
            int t = __shfl_up_sync(0xffffffffu, xv, d);
            if ((tid & 31) >= d) xv += t;
        }
        s[tid] = xv;
    }
    __syncthreads();
    if (tid < 64) {
        int add = (tid >= 32) ? s[31] : 0;
        s[tid] = s[tid] + add - ((tid < 49) ? g_blocksums[tid] : 0);
    }
    __syncthreads();
    int i = blockIdx.x * 1024 + tid;
    if (i < N_NODES) {
        int val = g_rowptr[i] + s[blockIdx.x];
        g_rowptr[i] = val;
        g_cursor[i] = val;
    }
    if (i == 0) g_rowptr[N_NODES] = E_EDGES;
}

__global__ void scatter_kernel(const int* __restrict__ src, const int* __restrict__ dst) {
    int e4 = blockIdx.x * blockDim.x + threadIdx.x;
    if (e4 < E_EDGES / 4) {
        int4 s = ((const int4*)src)[e4];
        int4 d = ((const int4*)dst)[e4];
        int p0 = atomicAdd(&g_cursor[d.x], 1); g_src_sorted[p0] = s.x;
        int p1 = atomicAdd(&g_cursor[d.y], 1); g_src_sorted[p1] = s.y;
        int p2 = atomicAdd(&g_cursor[d.z], 1); g_src_sorted[p2] = s.z;
        int p3 = atomicAdd(&g_cursor[d.w], 1); g_src_sorted[p3] = s.w;
    }
}

// ---------------------------------------------------------------------------
// fused per-node kernel: one warp per node, 2 edges/iter, plain softmax,
// 64-thread blocks. fs gathered as fp16 (uint2 per lane = 256 B/warp/edge).
// ---------------------------------------------------------------------------
__device__ __forceinline__ float4 load_fs_h(int u, int lane) {
    uint2 r = *((const uint2*)(g_fs_h + (size_t)u * F_DIM) + lane);
    __half2 h01 = *reinterpret_cast<__half2*>(&r.x);
    __half2 h23 = *reinterpret_cast<__half2*>(&r.y);
    float2 f01 = __half22float2(h01);
    float2 f23 = __half22float2(h23);
    return make_float4(f01.x, f01.y, f23.x, f23.y);
}

__device__ __forceinline__ float edge_logit(const float4 fsv, const float4 fdv,
                                            const float4 at) {
    float sx = fsv.x + fdv.x, sy = fsv.y + fdv.y;
    float sz = fsv.z + fdv.z, sw = fsv.w + fdv.w;
    sx = fmaxf(sx, NEG_SLOPE * sx);
    sy = fmaxf(sy, NEG_SLOPE * sy);
    sz = fmaxf(sz, NEG_SLOPE * sz);
    sw = fmaxf(sw, NEG_SLOPE * sw);
    float part = sx * at.x + sy * at.y + sz * at.z + sw * at.w;
    part += __shfl_xor_sync(0xffffffffu, part, 1);
    part += __shfl_xor_sync(0xffffffffu, part, 2);
    part += __shfl_xor_sync(0xffffffffu, part, 4);
    return part;
}

__global__ __launch_bounds__(64) void node_kernel(
    const float* __restrict__ attn,
    const float* __restrict__ out_bias,
    const float* __restrict__ ln_w,
    const float* __restrict__ ln_b,
    float* __restrict__ out)
{
    const int gwarp = blockIdx.x * 2 + (threadIdx.x >> 5);
    const int lane  = threadIdx.x & 31;
    if (gwarp >= N_NODES) return;
    const int v = gwarp;
    const int f = lane * 4;

    const float4 at  = *(const float4*)(attn + f);
    const float4 fdv = *(const float4*)(g_fd + (size_t)v * F_DIM + f);

    const int beg = g_rowptr[v];
    const int end = g_rowptr[v + 1];

    float4 acc = make_float4(0.f, 0.f, 0.f, 0.f);
    float  denom = 0.f;

    int p = beg;
    for (; p + 2 <= end; p += 2) {
        int u0 = g_src_sorted[p];
        int u1 = g_src_sorted[p + 1];
        float4 f0 = load_fs_h(u0, lane);
        float4 f1 = load_fs_h(u1, lane);
        float w0 = __expf(edge_logit(f0, fdv, at));
        float w1 = __expf(edge_logit(f1, fdv, at));
        denom += w0 + w1;
        acc.x += w0 * f0.x + w1 * f1.x;
        acc.y += w0 * f0.y + w1 * f1.y;
        acc.z += w0 * f0.z + w1 * f1.z;
        acc.w += w0 * f0.w + w1 * f1.w;
    }
    if (p < end) {
        int u0 = g_src_sorted[p];
        float4 f0 = load_fs_h(u0, lane);
        float w0 = __expf(edge_logit(f0, fdv, at));
        denom += w0;
        acc.x += w0 * f0.x;
        acc.y += w0 * f0.y;
        acc.z += w0 * f0.z;
        acc.w += w0 * f0.w;
    }

    float inv = (end > beg) ? (1.f / denom) : 0.f;
    float4 ob = *(const float4*)(out_bias + f);
    float4 h;
    h.x = acc.x * inv + ob.x;
    h.y = acc.y * inv + ob.y;
    h.z = acc.z * inv + ob.z;
    h.w = acc.w * inv + ob.w;

    float s1 = h.x + h.y + h.z + h.w;
#pragma unroll
    for (int d = 16; d >= 1; d >>= 1) s1 += __shfl_xor_sync(0xffffffffu, s1, d);
    float mean = s1 * (1.f / 128.f);

    float dx = h.x - mean, dy = h.y - mean, dz = h.z - mean, dw = h.w - mean;
    float s2 = dx * dx + dy * dy + dz * dz + dw * dw;
#pragma unroll
    for (int d = 16; d >= 1; d >>= 1) s2 += __shfl_xor_sync(0xffffffffu, s2, d);
    float rstd = rsqrtf(s2 * (1.f / 128.f) + LN_EPS);

    float4 w4 = *(const float4*)(ln_w + f);
    float4 b4 = *(const float4*)(ln_b + f);
    float4 o;
    o.x = dx * rstd * w4.x + b4.x;
    o.y = dy * rstd * w4.y + b4.y;
    o.z = dz * rstd * w4.z + b4.z;
    o.w = dw * rstd * w4.w + b4.w;
    o.x = (o.x > 0.f) ? o.x : expm1f(o.x);
    o.y = (o.y > 0.f) ? o.y : expm1f(o.y);
    o.z = (o.z > 0.f) ? o.z : expm1f(o.z);
    o.w = (o.w > 0.f) ? o.w : expm1f(o.w);

    *(float4*)(out + (size_t)v * F_DIM + f) = o;
}

// ---------------------------------------------------------------------------
// launch  (gemm at index 3 -> profiled)
// ---------------------------------------------------------------------------
extern "C" void kernel_launch(void* const* d_in, const int* in_sizes, int n_in,
                              void* d_out, int out_size)
{
    const float* x        = (const float*)d_in[0];
    const float* W_src    = (const float*)d_in[1];
    const float* b_src    = (const float*)d_in[2];
    const float* W_dst    = (const float*)d_in[3];
    const float* b_dst    = (const float*)d_in[4];
    const float* attn     = (const float*)d_in[5];
    const float* out_bias = (const float*)d_in[6];
    const float* ln_w     = (const float*)d_in[7];
    const float* ln_b     = (const float*)d_in[8];
    const int*   src      = (const int*)d_in[9];
    const int*   dst      = (const int*)d_in[10];
    float* out = (float*)d_out;

    cudaFuncSetAttribute(gemm_mma_kernel,
                         cudaFuncAttributeMaxDynamicSharedMemorySize, SM_TOTAL);

    prep_kernel<<<PREP_BLOCKS, 256>>>(x, W_src, W_dst, dst);             // 0
    scan1_kernel<<<49, 1024>>>();                                        // 1
    scan3_kernel<<<49, 1024>>>();                                        // 2
    gemm_mma_kernel<<<148, 256, SM_TOTAL>>>(b_src, b_dst);               // 3 (profiled)
    scatter_kernel<<<(E_EDGES / 4 + 255) / 256, 256>>>(src, dst);        // 4
    node_kernel<<<(N_NODES + 1) / 2, 64>>>(attn, out_bias, ln_w, ln_b, out); // 5
}

// round 14
// speedup vs baseline: 1.0584x; 1.0584x over previous
#include <cuda_runtime.h>
#include <cuda_bf16.h>
#include <math.h>
#include <stdint.h>

// ---------------------------------------------------------------------------
// GATv2 layer. GEMMs via mma.sync bf16 (3-term hi/lo split, fp32 accum),
// term-outer mainloop, cp.async double-buffered A, pre-split x.
// Node: warp/node, 2 edges/iter, plain softmax, index-prefetch pipeline.
// ---------------------------------------------------------------------------

#define N_NODES 50000
#define E_EDGES 800000
#define F_DIM   128
#define NEG_SLOPE 0.2f
#define LN_EPS  1e-12f
#define NT64    ((N_NODES + 63) / 64)    // 782 tiles of 64 rows

#define CX_BLOCKS   6250
#define CW_BLOCKS   2
#define HIST_BLOCKS 782
#define PREP_BLOCKS (CX_BLOCKS + CW_BLOCKS + HIST_BLOCKS)

// ---- device scratch ----
__device__ float g_fs[(size_t)N_NODES * F_DIM];
__device__ float g_fd[(size_t)N_NODES * F_DIM];
__device__ int   g_deg[N_NODES];          // static-zero on call 1; scan1 re-zeros
__device__ int   g_rowptr[N_NODES + 1];
__device__ int   g_cursor[N_NODES];
__device__ int   g_src_sorted[E_EDGES];
__device__ int   g_blocksums[64];
__device__ __nv_bfloat16 g_wt_hi[2][128 * 128];
__device__ __nv_bfloat16 g_wt_lo[2][128 * 128];
__device__ __nv_bfloat16 g_x_hi[(size_t)N_NODES * F_DIM];
__device__ __nv_bfloat16 g_x_lo[(size_t)N_NODES * F_DIM];

__device__ __forceinline__ uint32_t smem_u32(const void* p) {
    uint32_t a;
    asm("{ .reg .u64 t; cvta.to.shared.u64 t, %1; cvt.u32.u64 %0, t; }"
        : "=r"(a) : "l"(p));
    return a;
}
__device__ __forceinline__ uint32_t pack2(float a, float b) {
    __nv_bfloat162 t = __floats2bfloat162_rn(a, b);
    return *reinterpret_cast<uint32_t*>(&t);
}
__device__ __forceinline__ void ldsm_x4(uint32_t* r, uint32_t addr) {
    asm volatile("ldmatrix.sync.aligned.m8n8.x4.shared.b16 {%0,%1,%2,%3}, [%4];"
                 : "=r"(r[0]), "=r"(r[1]), "=r"(r[2]), "=r"(r[3]) : "r"(addr));
}
__device__ __forceinline__ void mma_bf16(float* d, const uint32_t* a,
                                         uint32_t b0, uint32_t b1) {
    asm volatile(
        "mma.sync.aligned.m16n8k16.row.col.f32.bf16.bf16.f32 "
        "{%0,%1,%2,%3}, {%4,%5,%6,%7}, {%8,%9}, {%0,%1,%2,%3};"
        : "+f"(d[0]), "+f"(d[1]), "+f"(d[2]), "+f"(d[3])
        : "r"(a[0]), "r"(a[1]), "r"(a[2]), "r"(a[3]), "r"(b0), "r"(b1));
}
__device__ __forceinline__ void cp_async16(uint32_t saddr, const void* gaddr, int srcsz) {
    asm volatile("cp.async.cg.shared.global [%0], [%1], 16, %2;"
                 :: "r"(saddr), "l"(gaddr), "r"(srcsz) : "memory");
}
#define CP_COMMIT() asm volatile("cp.async.commit_group;" ::: "memory")
#define CP_WAIT1()  asm volatile("cp.async.wait_group 1;" ::: "memory")

// ---------------------------------------------------------------------------
// prep: convert_x | convert_w | hist
// ---------------------------------------------------------------------------
__global__ __launch_bounds__(256) void prep_kernel(
    const float* __restrict__ x,
    const float* __restrict__ Wsrc, const float* __restrict__ Wdst,
    const int* __restrict__ dst)
{
    const int b = blockIdx.x, tid = threadIdx.x;
    if (b < CX_BLOCKS) {
        size_t i4 = (size_t)b * 256 + tid;
        float4 v = ((const float4*)x)[i4];
        __nv_bfloat162 h01 = __floats2bfloat162_rn(v.x, v.y);
        __nv_bfloat162 h23 = __floats2bfloat162_rn(v.z, v.w);
        uint2 hi, lo;
        hi.x = *reinterpret_cast<uint32_t*>(&h01);
        hi.y = *reinterpret_cast<uint32_t*>(&h23);
        lo.x = pack2(v.x - __bfloat162float(h01.x), v.y - __bfloat162float(h01.y));
        lo.y = pack2(v.z - __bfloat162float(h23.x), v.w - __bfloat162float(h23.y));
        ((uint2*)g_x_hi)[i4] = hi;
        ((uint2*)g_x_lo)[i4] = lo;
    } else if (b < CX_BLOCKS + CW_BLOCKS) {
        const int w = b - CX_BLOCKS;
        const float* W = w == 0 ? Wsrc : Wdst;
        for (int idx = tid; idx < 128 * 128; idx += 256) {
            int k = idx >> 7, n = idx & 127;
            float v = W[idx];
            __nv_bfloat16 hi = __float2bfloat16(v);
            float r = v - __bfloat162float(hi);
            g_wt_hi[w][n * 128 + k] = hi;
            g_wt_lo[w][n * 128 + k] = __float2bfloat16(r);
        }
    } else {
        int e4 = (b - CX_BLOCKS - CW_BLOCKS) * 256 + tid;
        if (e4 < E_EDGES / 4) {
            int4 d = ((const int4*)dst)[e4];
            atomicAdd(&g_deg[d.x], 1);
            atomicAdd(&g_deg[d.y], 1);
            atomicAdd(&g_deg[d.z], 1);
            atomicAdd(&g_deg[d.w], 1);
        }
    }
}

// ---------------------------------------------------------------------------
// Persistent GEMM (R9/R11-proven): 148 CTAs, 1/SM; both projections per CTA.
// ---------------------------------------------------------------------------
#define PAD   136
#define A_IMG (64 * PAD)
#define B_IMG (128 * PAD)
#define B_BASE (4 * A_IMG)
#define SM_TOTAL ((4 * A_IMG + 4 * B_IMG) * 2)   // 208896 bytes

__global__ __launch_bounds__(256, 1) void gemm_mma_kernel(
    const float* __restrict__ bsrc, const float* __restrict__ bdst)
{
    extern __shared__ __nv_bfloat16 sm[];
    const int tid = threadIdx.x, wid = tid >> 5, lane = tid & 31;
    const int wm = wid >> 2, wn = wid & 3;
    const uint32_t sbase = smem_u32(sm);

    for (int i = tid; i < 2048; i += 256) {
        int n = i >> 4, k = (i & 15) << 3;
        *(float4*)(sm + B_BASE + 0 * B_IMG + n * PAD + k) = *(const float4*)(g_wt_hi[0] + n * 128 + k);
        *(float4*)(sm + B_BASE + 1 * B_IMG + n * PAD + k) = *(const float4*)(g_wt_lo[0] + n * 128 + k);
        *(float4*)(sm + B_BASE + 2 * B_IMG + n * PAD + k) = *(const float4*)(g_wt_hi[1] + n * 128 + k);
        *(float4*)(sm + B_BASE + 3 * B_IMG + n * PAD + k) = *(const float4*)(g_wt_lo[1] + n * 128 + k);
    }

    auto prefetch = [&](int tile, int buf) {
        const int row0 = tile * 64;
#pragma unroll
        for (int img = 0; img < 2; img++) {
            const __nv_bfloat16* gx = img ? g_x_lo : g_x_hi;
            uint32_t base = sbase + (uint32_t)((buf * 2 + img) * A_IMG) * 2;
#pragma unroll
            for (int i = tid; i < 1024; i += 256) {
                int row = i >> 4, ch = (i & 15) << 3;
                int gr = row0 + row;
                int sz = (gr < N_NODES) ? 16 : 0;
                cp_async16(base + (uint32_t)(row * PAD + ch) * 2,
                           gx + (size_t)gr * F_DIM + ch, sz);
            }
        }
    };

    const int g = lane >> 3, l7 = lane & 7;
    const int tile0 = blockIdx.x;

    prefetch(tile0, 0);
    CP_COMMIT();

    int ibuf = 0;
    for (int tile = tile0; tile < NT64; tile += 148, ibuf ^= 1) {
        int tnext = tile + 148;
        if (tnext < NT64) prefetch(tnext, ibuf ^ 1);
        CP_COMMIT();
        CP_WAIT1();
        __syncthreads();

        const int row0 = tile * 64;
        const uint32_t ahi = sbase + (uint32_t)((ibuf * 2 + 0) * A_IMG) * 2;
        const uint32_t alo = sbase + (uint32_t)((ibuf * 2 + 1) * A_IMG) * 2;

        for (int wsel = 0; wsel < 2; wsel++) {
            float acc[2][4][4];
#pragma unroll
            for (int i = 0; i < 2; i++)
#pragma unroll
                for (int j = 0; j < 4; j++)
#pragma unroll
                    for (int q = 0; q < 4; q++) acc[i][j][q] = 0.f;

#pragma unroll
            for (int term = 0; term < 3; term++) {
                const uint32_t abase = (term == 2) ? alo : ahi;
                const uint32_t bbase = sbase +
                    (uint32_t)(B_BASE + (wsel * 2 + (term == 1)) * B_IMG) * 2;
#pragma unroll
                for (int k0 = 0; k0 < 128; k0 += 16) {
                    uint32_t afr[2][4];
#pragma unroll
                    for (int mt = 0; mt < 2; mt++) {
                        int r = wm * 32 + mt * 16 + ((g & 1) << 3) + l7;
                        int c = k0 + ((g >> 1) << 3);
                        ldsm_x4(afr[mt], abase + (uint32_t)(r * PAD + c) * 2);
                    }
#pragma unroll
                    for (int nt = 0; nt < 2; nt++) {
                        int r = wn * 32 + nt * 16 + ((g >> 1) << 3) + l7;
                        int c = k0 + ((g & 1) << 3);
                        uint32_t bfr[4];
                        ldsm_x4(bfr, bbase + (uint32_t)(r * PAD + c) * 2);
#pragma unroll
                        for (int mt = 0; mt < 2; mt++) {
                            mma_bf16(acc[mt][nt * 2],     afr[mt], bfr[0], bfr[1]);
                            mma_bf16(acc[mt][nt * 2 + 1], afr[mt], bfr[2], bfr[3]);
                        }
                    }
                }
            }

            const float* bias = wsel ? bdst : bsrc;
            float* outp = wsel ? g_fd : g_fs;
#pragma unroll
            for (int mt = 0; mt < 2; mt++) {
#pragma unroll
                for (int j = 0; j < 4; j++) {
                    int col = wn * 32 + (j >> 1) * 16 + (j & 1) * 8 + (lane & 3) * 2;
                    float bx = bias[col], by = bias[col + 1];
                    int r0 = row0 + wm * 32 + mt * 16 + (lane >> 2);
                    if (r0 < N_NODES) {
                        float2 o = make_float2(acc[mt][j][0] + bx, acc[mt][j][1] + by);
                        *(float2*)(outp + (size_t)r0 * F_DIM + col) = o;
                    }
                    int r1 = r0 + 8;
                    if (r1 < N_NODES) {
                        float2 o = make_float2(acc[mt][j][2] + bx, acc[mt][j][3] + by);
                        *(float2*)(outp + (size_t)r1 * F_DIM + col) = o;
                    }
                }
            }
        }
        __syncthreads();
    }
}

// ---------------------------------------------------------------------------
// scan1: block-local exclusive scan of degrees; RESETS g_deg for next call.
// ---------------------------------------------------------------------------
__global__ __launch_bounds__(1024) void scan1_kernel() {
    __shared__ int ws[32];
    const int tid = threadIdx.x, lane = tid & 31, wid = tid >> 5;
    int i = blockIdx.x * 1024 + tid;
    int v = 0;
    if (i < N_NODES) { v = g_deg[i]; g_deg[i] = 0; }
    int xv = v;
#pragma unroll
    for (int d = 1; d < 32; d <<= 1) {
        int t = __shfl_up_sync(0xffffffffu, xv, d);
        if (lane >= d) xv += t;
    }
    if (lane == 31) ws[wid] = xv;
    __syncthreads();
    if (wid == 0) {
        int y = ws[lane];
#pragma unroll
        for (int d = 1; d < 32; d <<= 1) {
            int t = __shfl_up_sync(0xffffffffu, y, d);
            if (lane >= d) y += t;
        }
        ws[lane] = y;
    }
    __syncthreads();
    int off = (wid > 0) ? ws[wid - 1] : 0;
    int incl = xv + off;
    if (i < N_NODES) g_rowptr[i] = incl - v;
    if (tid == 1023) g_blocksums[blockIdx.x] = incl;
}

// ---------------------------------------------------------------------------
// scan3: inline scan of 49 block sums + fixup.
// ---------------------------------------------------------------------------
__global__ __launch_bounds__(1024) void scan3_kernel() {
    __shared__ int s[64];
    const int tid = threadIdx.x;
    if (tid < 64) {
        int v = (tid < 49) ? g_blocksums[tid] : 0;
        int xv = v;
#pragma unroll
        for (int d = 1; d < 32; d <<= 1) {
            int t = __shfl_up_sync(0xffffffffu, xv, d);
            if ((tid & 31) >= d) xv += t;
        }
        s[tid] = xv;
    }
    __syncthreads();
    if (tid < 64) {
        int add = (tid >= 32) ? s[31] : 0;
        s[tid] = s[tid] + add - ((tid < 49) ? g_blocksums[tid] : 0);
    }
    __syncthreads();
    int i = blockIdx.x * 1024 + tid;
    if (i < N_NODES) {
        int val = g_rowptr[i] + s[blockIdx.x];
        g_rowptr[i] = val;
        g_cursor[i] = val;
    }
    if (i == 0) g_rowptr[N_NODES] = E_EDGES;
}

__global__ void scatter_kernel(const int* __restrict__ src, const int* __restrict__ dst) {
    int e4 = blockIdx.x * blockDim.x + threadIdx.x;
    if (e4 < E_EDGES / 4) {
        int4 s = ((const int4*)src)[e4];
        int4 d = ((const int4*)dst)[e4];
        int p0 = atomicAdd(&g_cursor[d.x], 1); g_src_sorted[p0] = s.x;
        int p1 = atomicAdd(&g_cursor[d.y], 1); g_src_sorted[p1] = s.y;
        int p2 = atomicAdd(&g_cursor[d.z], 1); g_src_sorted[p2] = s.z;
        int p3 = atomicAdd(&g_cursor[d.w], 1); g_src_sorted[p3] = s.w;
    }
}

// ---------------------------------------------------------------------------
// fused per-node kernel: one warp per node, 2 edges/iter, plain softmax,
// 64-thread blocks, INDEX-PREFETCH pipeline (breaks idx->gather chain).
// ---------------------------------------------------------------------------
__device__ __forceinline__ float edge_logit(const float4 fsv, const float4 fdv,
                                            const float4 at) {
    float sx = fsv.x + fdv.x, sy = fsv.y + fdv.y;
    float sz = fsv.z + fdv.z, sw = fsv.w + fdv.w;
    sx = fmaxf(sx, NEG_SLOPE * sx);
    sy = fmaxf(sy, NEG_SLOPE * sy);
    sz = fmaxf(sz, NEG_SLOPE * sz);
    sw = fmaxf(sw, NEG_SLOPE * sw);
    float part = sx * at.x + sy * at.y + sz * at.z + sw * at.w;
    part += __shfl_xor_sync(0xffffffffu, part, 1);
    part += __shfl_xor_sync(0xffffffffu, part, 2);
    part += __shfl_xor_sync(0xffffffffu, part, 4);
    return part;
}

__global__ __launch_bounds__(64) void node_kernel(
    const float* __restrict__ attn,
    const float* __restrict__ out_bias,
    const float* __restrict__ ln_w,
    const float* __restrict__ ln_b,
    float* __restrict__ out)
{
    const int gwarp = blockIdx.x * 2 + (threadIdx.x >> 5);
    const int lane  = threadIdx.x & 31;
    if (gwarp >= N_NODES) return;
    const int v = gwarp;
    const int f = lane * 4;

    const float4 at  = *(const float4*)(attn + f);
    const float4 fdv = *(const float4*)(g_fd + (size_t)v * F_DIM + f);

    const int beg = g_rowptr[v];
    const int end = g_rowptr[v + 1];

    float4 acc = make_float4(0.f, 0.f, 0.f, 0.f);
    float  denom = 0.f;

    // index prefetch pipeline: iteration i's indices are loaded in iteration i-1
    int p = beg;
    int u0 = (p     < end) ? g_src_sorted[p]     : 0;
    int u1 = (p + 1 < end) ? g_src_sorted[p + 1] : 0;

    for (; p + 2 <= end; ) {
        const int c0 = u0, c1 = u1;
        p += 2;
        if (p     < end) u0 = g_src_sorted[p];
        if (p + 1 < end) u1 = g_src_sorted[p + 1];

        float4 f0 = *(const float4*)(g_fs + (size_t)c0 * F_DIM + f);
        float4 f1 = *(const float4*)(g_fs + (size_t)c1 * F_DIM + f);
        float w0 = __expf(edge_logit(f0, fdv, at));
        float w1 = __expf(edge_logit(f1, fdv, at));
        denom += w0 + w1;
        acc.x += w0 * f0.x + w1 * f1.x;
        acc.y += w0 * f0.y + w1 * f1.y;
        acc.z += w0 * f0.z + w1 * f1.z;
        acc.w += w0 * f0.w + w1 * f1.w;
    }
    if (p < end) {
        float4 f0 = *(const float4*)(g_fs + (size_t)u0 * F_DIM + f);
        float w0 = __expf(edge_logit(f0, fdv, at));
        denom += w0;
        acc.x += w0 * f0.x;
        acc.y += w0 * f0.y;
        acc.z += w0 * f0.z;
        acc.w += w0 * f0.w;
    }

    float inv = (end > beg) ? (1.f / denom) : 0.f;
    float4 ob = *(const float4*)(out_bias + f);
    float4 h;
    h.x = acc.x * inv + ob.x;
    h.y = acc.y * inv + ob.y;
    h.z = acc.z * inv + ob.z;
    h.w = acc.w * inv + ob.w;

    float s1 = h.x + h.y + h.z + h.w;
#pragma unroll
    for (int d = 16; d >= 1; d >>= 1) s1 += __shfl_xor_sync(0xffffffffu, s1, d);
    float mean = s1 * (1.f / 128.f);

    float dx = h.x - mean, dy = h.y - mean, dz = h.z - mean, dw = h.w - mean;
    float s2 = dx * dx + dy * dy + dz * dz + dw * dw;
#pragma unroll
    for (int d = 16; d >= 1; d >>= 1) s2 += __shfl_xor_sync(0xffffffffu, s2, d);
    float rstd = rsqrtf(s2 * (1.f / 128.f) + LN_EPS);

    float4 w4 = *(const float4*)(ln_w + f);
    float4 b4 = *(const float4*)(ln_b + f);
    float4 o;
    o.x = dx * rstd * w4.x + b4.x;
    o.y = dy * rstd * w4.y + b4.y;
    o.z = dz * rstd * w4.z + b4.z;
    o.w = dw * rstd * w4.w + b4.w;
    o.x = (o.x > 0.f) ? o.x : expm1f(o.x);
    o.y = (o.y > 0.f) ? o.y : expm1f(o.y);
    o.z = (o.z > 0.f) ? o.z : expm1f(o.z);
    o.w = (o.w > 0.f) ? o.w : expm1f(o.w);

    *(float4*)(out + (size_t)v * F_DIM + f) = o;
}

// ---------------------------------------------------------------------------
// launch  (gemm at index 3 -> profiled)
// ---------------------------------------------------------------------------
extern "C" void kernel_launch(void* const* d_in, const int* in_sizes, int n_in,
                              void* d_out, int out_size)
{
    const float* x        = (const float*)d_in[0];
    const float* W_src    = (const float*)d_in[1];
    const float* b_src    = (const float*)d_in[2];
    const float* W_dst    = (const float*)d_in[3];
    const float* b_dst    = (const float*)d_in[4];
    const float* attn     = (const float*)d_in[5];
    const float* out_bias = (const float*)d_in[6];
    const float* ln_w     = (const float*)d_in[7];
    const float* ln_b     = (const float*)d_in[8];
    const int*   src      = (const int*)d_in[9];
    const int*   dst      = (const int*)d_in[10];
    float* out = (float*)d_out;

    cudaFuncSetAttribute(gemm_mma_kernel,
                         cudaFuncAttributeMaxDynamicSharedMemorySize, SM_TOTAL);

    prep_kernel<<<PREP_BLOCKS, 256>>>(x, W_src, W_dst, dst);             // 0
    scan1_kernel<<<49, 1024>>>();                                        // 1
    scan3_kernel<<<49, 1024>>>();                                        // 2
    gemm_mma_kernel<<<148, 256, SM_TOTAL>>>(b_src, b_dst);               // 3 (profiled)
    scatter_kernel<<<(E_EDGES / 4 + 255) / 256, 256>>>(src, dst);        // 4
    node_kernel<<<(N_NODES + 1) / 2, 64>>>(attn, out_bias, ln_w, ln_b, out); // 5
}